// round 5
// baseline (speedup 1.0000x reference)
#include <cuda_runtime.h>
#include <math.h>

// ChordalPCWeightTransform: the two per-label rolls compose to identity on the
// data and a rotation on the weight vector:
//   out[b,l,p] = softmax_p( x[b,l,p] * w[(p - root) mod 12] ), p<12; w[12] at p=12
//   root = (l / 12) mod 12,  l = row % 144
// Pure streaming kernel: float4-staged loads/stores through shared memory,
// per-thread 13-wide softmax in registers.

#define P 13
#define ROWS_PER_BLOCK 256
#define TILE_FLOATS (ROWS_PER_BLOCK * P)      // 3328 floats = 13312 bytes (16B aligned)
#define TILE_VEC4 (TILE_FLOATS / 4)           // 832 float4

__global__ __launch_bounds__(ROWS_PER_BLOCK)
void chordal_softmax_kernel(const float* __restrict__ x,
                            const float* __restrict__ w,
                            float* __restrict__ out)
{
    __shared__ float tile[TILE_FLOATS];
    __shared__ float ws[P];

    const int tid = threadIdx.x;
    if (tid < P) ws[tid] = w[tid];

    const long long base = (long long)blockIdx.x * TILE_FLOATS;

    // ---- vectorized load: global -> smem ----
    const float4* __restrict__ gx = (const float4*)(x + base);
    float4* sv = (float4*)tile;
#pragma unroll
    for (int i = 0; i < 4; i++) {
        int idx = tid + i * ROWS_PER_BLOCK;
        if (idx < TILE_VEC4) sv[idx] = gx[idx];
    }
    __syncthreads();

    // ---- per-row weighted softmax ----
    const int row = blockIdx.x * ROWS_PER_BLOCK + tid;   // global row index
    const int root = (row / 12) % 12;                    // == (row % 144) / 12

    float v[P];
    float m = -INFINITY;
#pragma unroll
    for (int p = 0; p < P; p++) {
        int wi;
        if (p == 12) {
            wi = 12;
        } else {
            wi = p - root;
            if (wi < 0) wi += 12;
        }
        v[p] = tile[tid * P + p] * ws[wi];
        m = fmaxf(m, v[p]);
    }

    float s = 0.0f;
#pragma unroll
    for (int p = 0; p < P; p++) {
        v[p] = __expf(v[p] - m);
        s += v[p];
    }
    const float r = __frcp_rn(s);

    __syncthreads();   // all reads of tile done; safe to overwrite
#pragma unroll
    for (int p = 0; p < P; p++) {
        tile[tid * P + p] = v[p] * r;
    }
    __syncthreads();

    // ---- vectorized store: smem -> global ----
    float4* __restrict__ go = (float4*)(out + base);
#pragma unroll
    for (int i = 0; i < 4; i++) {
        int idx = tid + i * ROWS_PER_BLOCK;
        if (idx < TILE_VEC4) go[idx] = sv[idx];
    }
}

extern "C" void kernel_launch(void* const* d_in, const int* in_sizes, int n_in,
                              void* d_out, int out_size)
{
    const float* x = (const float*)d_in[0];   // chordal_pc_vector [65536,144,13]
    const float* w = (const float*)d_in[1];   // scale_degree_weight [13]
    float* out = (float*)d_out;

    // total rows = in_sizes[0] / 13; 65536*144 = 9,437,184 rows -> 36,864 blocks
    const long long total = (long long)in_sizes[0];
    const int nblocks = (int)(total / TILE_FLOATS);

    chordal_softmax_kernel<<<nblocks, ROWS_PER_BLOCK>>>(x, w, out);
}

// round 8
// speedup vs baseline: 1.0004x; 1.0004x over previous
#include <cuda_runtime.h>
#include <math.h>

// ChordalPCWeightTransform: the two per-label rolls compose to identity on the
// data and a rotation on the weight vector:
//   out[b,l,p] = softmax_p( x[b,l,p] * w[(p - root) mod 12] ), p<12; w[12] at p=12
//   root = (l / 12) mod 12,  l = row % 144
//
// Streaming kernel: float4-staged loads/stores through shared memory,
// per-thread 13-wide softmax in registers. R5: evict-first/streaming cache
// hints (read-once/write-once data), removed redundant middle barrier
// (compute phase reads+writes only the thread's own row), unpredicated
// staging main loop.

#define P 13
#define ROWS_PER_BLOCK 256
#define TILE_FLOATS (ROWS_PER_BLOCK * P)      // 3328 floats = 13312 bytes (16B aligned)
#define TILE_VEC4 (TILE_FLOATS / 4)           // 832 float4 (= 3*256 + 64)

__global__ __launch_bounds__(ROWS_PER_BLOCK)
void chordal_softmax_kernel(const float* __restrict__ x,
                            const float* __restrict__ w,
                            float* __restrict__ out)
{
    __shared__ float tile[TILE_FLOATS];
    __shared__ float ws[P];

    const int tid = threadIdx.x;
    if (tid < P) ws[tid] = __ldg(&w[tid]);

    const long long base = (long long)blockIdx.x * TILE_FLOATS;

    // ---- vectorized load: global -> smem (evict-first: read-once data) ----
    const float4* __restrict__ gx = (const float4*)(x + base);
    float4* sv = (float4*)tile;
    {
        // 3 full iterations, no predicate (768 vec4), then 64-thread tail.
        float4 a0 = __ldcs(&gx[tid]);
        float4 a1 = __ldcs(&gx[tid + 256]);
        float4 a2 = __ldcs(&gx[tid + 512]);
        float4 a3;
        if (tid < 64) a3 = __ldcs(&gx[tid + 768]);
        sv[tid]       = a0;
        sv[tid + 256] = a1;
        sv[tid + 512] = a2;
        if (tid < 64) sv[tid + 768] = a3;
    }
    __syncthreads();

    // ---- per-row weighted softmax (row owned exclusively by this thread) ----
    const int row  = blockIdx.x * ROWS_PER_BLOCK + tid;  // global row index
    const int root = (row / 12) % 12;                    // == (row % 144) / 12

    float v[P];
    float m = -INFINITY;
#pragma unroll
    for (int p = 0; p < P; p++) {
        int wi;
        if (p == 12) {
            wi = 12;
        } else {
            wi = p - root;
            if (wi < 0) wi += 12;
        }
        v[p] = tile[tid * P + p] * ws[wi];
        m = fmaxf(m, v[p]);
    }

    float s = 0.0f;
#pragma unroll
    for (int p = 0; p < P; p++) {
        v[p] = __expf(v[p] - m);
        s += v[p];
    }
    const float r = __frcp_rn(s);

    // No barrier needed here: this thread reads and overwrites ONLY its own
    // 13 floats (tile[tid*13 .. tid*13+12]); no cross-thread hazard.
#pragma unroll
    for (int p = 0; p < P; p++) {
        tile[tid * P + p] = v[p] * r;
    }
    __syncthreads();   // others' rows must be written before vectorized readback

    // ---- vectorized store: smem -> global (streaming: write-once data) ----
    float4* __restrict__ go = (float4*)(out + base);
    {
        float4 b0 = sv[tid];
        float4 b1 = sv[tid + 256];
        float4 b2 = sv[tid + 512];
        __stcs(&go[tid],       b0);
        __stcs(&go[tid + 256], b1);
        __stcs(&go[tid + 512], b2);
        if (tid < 64) {
            float4 b3 = sv[tid + 768];
            __stcs(&go[tid + 768], b3);
        }
    }
}

extern "C" void kernel_launch(void* const* d_in, const int* in_sizes, int n_in,
                              void* d_out, int out_size)
{
    const float* x = (const float*)d_in[0];   // chordal_pc_vector [65536,144,13]
    const float* w = (const float*)d_in[1];   // scale_degree_weight [13]
    float* out = (float*)d_out;

    const long long total = (long long)in_sizes[0];   // 65536*144*13
    const int nblocks = (int)(total / TILE_FLOATS);   // 36864

    chordal_softmax_kernel<<<nblocks, ROWS_PER_BLOCK>>>(x, w, out);
}